// round 14
// baseline (speedup 1.0000x reference)
#include <cuda_runtime.h>
#include <cuda_bf16.h>
#include <math.h>
#include <stdint.h>

// Problem constants (fixed-shape problem)
#define B_  64
#define S_  512
#define H_  768
#define U_  16
#define C_  5
#define NSEG (B_ * U_)       // 1024
#define NTILE_N 8            // 768 / 96
#define NTILE_M 16           // 1024 / 64
#define NTILE_P (NTILE_N * 2)  // 16 partial slots (48-col warp slices)
#define NWPREP  576          // 24 x 24 transpose blocks
#define NCHKBLK 1024         // 64 batches x 16 row-chunks of 32

// ---------------------------------------------------------------------------
// Scratch (no allocation allowed; __device__ globals are zero-initialized)
// ---------------------------------------------------------------------------
__device__ __align__(16) float g_sum[NSEG * H_];     // fp32 segment sums
__device__ unsigned int g_cnt[NSEG];                  // segment counts
__device__ __align__(16) __nv_bfloat16 g_mean_hi[NSEG * H_];
__device__ __align__(16) __nv_bfloat16 g_mean_lo[NSEG * H_];
__device__ __align__(16) __nv_bfloat16 g_wt_hi[H_ * H_];   // W_h^T: [n][k]
__device__ __align__(16) __nv_bfloat16 g_wt_lo[H_ * H_];
__device__ float g_partial[NTILE_P * NSEG * C_];
__device__ unsigned int g_arrive[NTILE_M];   // zero-init; self-resetting

// ---------------------------------------------------------------------------
// PTX helpers (baseline PTX only — compiles for compute_103)
// ---------------------------------------------------------------------------
__device__ __forceinline__ void mma_bf16(float* c, const uint32_t* a,
                                         const uint32_t* b) {
    asm volatile(
        "mma.sync.aligned.m16n8k16.row.col.f32.bf16.bf16.f32 "
        "{%0,%1,%2,%3}, {%4,%5,%6,%7}, {%8,%9}, {%0,%1,%2,%3};\n"
        : "+f"(c[0]), "+f"(c[1]), "+f"(c[2]), "+f"(c[3])
        : "r"(a[0]), "r"(a[1]), "r"(a[2]), "r"(a[3]), "r"(b[0]), "r"(b[1]));
}
__device__ __forceinline__ void ldsm_x4(uint32_t* r, uint32_t addr) {
    asm volatile(
        "ldmatrix.sync.aligned.m8n8.x4.shared.b16 {%0,%1,%2,%3}, [%4];"
        : "=r"(r[0]), "=r"(r[1]), "=r"(r[2]), "=r"(r[3]) : "r"(addr));
}
#define CP16(dst, src) \
    asm volatile("cp.async.cg.shared.global [%0], [%1], 16;" \
                 :: "r"(dst), "l"(src))
#define CP_COMMIT() asm volatile("cp.async.commit_group;" ::: "memory")
__device__ __forceinline__ uint32_t s2u(const void* p) {
    return (uint32_t)__cvta_generic_to_shared(p);
}

// ---------------------------------------------------------------------------
// Kernel P1: balanced accumulation + W_h prep.  block = 384.
//   blocks [0, NCHKBLK): fixed 32 rows of one batch -> per-run fp32 sums via
//     atomicAdd into g_sum, counts via g_cnt.  Perfect load balance.
//   blocks [NCHKBLK, NCHKBLK+NWPREP): W_h transpose + bf16 split.
// ---------------------------------------------------------------------------
__global__ __launch_bounds__(384) void prep1_kernel(
    const float* __restrict__ hidden, const int* __restrict__ seg,
    const float* __restrict__ W) {
    const int bid = blockIdx.x;
    const int tid = threadIdx.x;

    if (bid < NCHKBLK) {
        const int b = bid >> 4, c = bid & 15;
        const int row0 = c * 32;             // within batch
        __shared__ int ids[32];
        if (tid < 32) {
            int id = seg[(size_t)b * S_ + row0 + tid];
            ids[tid] = id;
            atomicAdd(&g_cnt[b * U_ + id], 1u);
        }
        __syncthreads();

        const int gcol = tid % 192;          // float4 column
        const int grp  = tid / 192;          // 0: even rows, 1: odd rows
        const float4* __restrict__ hp =
            (const float4*)hidden + ((size_t)b * S_ + row0) * (H_ / 4) + gcol;

        float4 acc = {0, 0, 0, 0};
        #pragma unroll
        for (int r = grp; r < 32; r += 2) {
            float4 v = hp[(size_t)r * (H_ / 4)];
            acc.x += v.x; acc.y += v.y; acc.z += v.z; acc.w += v.w;
            // sorted ids: run end (for this parity) iff id changes 2 ahead
            if (r + 2 >= 32 || ids[r + 2] != ids[r]) {
                float* dst = g_sum + ((size_t)(b * U_ + ids[r]) * H_) + gcol * 4;
                atomicAdd(dst + 0, acc.x);
                atomicAdd(dst + 1, acc.y);
                atomicAdd(dst + 2, acc.z);
                atomicAdd(dst + 3, acc.w);
                acc.x = 0; acc.y = 0; acc.z = 0; acc.w = 0;
            }
        }
    } else {
        // ---- W_h transpose + split (256 active threads) ----
        __shared__ float t[32][33];
        const int w  = bid - NCHKBLK;
        const int n0 = (w % 24) * 32, k0 = (w / 24) * 32;
        if (tid < 256) {
            const int tx = tid & 31, ty = tid >> 5;
            #pragma unroll
            for (int r = 0; r < 32; r += 8)
                t[ty + r][tx] = W[(size_t)(k0 + ty + r) * H_ + n0 + tx];
        }
        __syncthreads();
        if (tid < 256) {
            const int tx = tid & 31, ty = tid >> 5;
            const int k = k0 + tx;
            #pragma unroll
            for (int r = 0; r < 32; r += 8) {
                const int n = n0 + ty + r;
                float v = t[tx][ty + r];
                __nv_bfloat16 hi = __float2bfloat16(v);
                __nv_bfloat16 lo = __float2bfloat16(v - __bfloat162float(hi));
                g_wt_hi[(size_t)n * H_ + k] = hi;
                g_wt_lo[(size_t)n * H_ + k] = lo;
            }
        }
    }
}

// ---------------------------------------------------------------------------
// Kernel P2: finalize means (divide + bf16 hi/lo split) and SELF-CLEAN the
// fp32 accumulators for the next graph replay.  grid = NSEG, block = 192.
// ---------------------------------------------------------------------------
__global__ __launch_bounds__(192) void prep2_kernel() {
    const int sgi = blockIdx.x;
    const int col = threadIdx.x;   // float4 column

    const float inv = 1.0f / fmaxf((float)g_cnt[sgi], 1.0f);
    float4* sp = (float4*)(g_sum + (size_t)sgi * H_) + col;
    float4 s = *sp;

    float m[4] = {s.x * inv, s.y * inv, s.z * inv, s.w * inv};

    __nv_bfloat16 hi[4], lo[4];
    #pragma unroll
    for (int i = 0; i < 4; ++i) {
        hi[i] = __float2bfloat16(m[i]);
        lo[i] = __float2bfloat16(m[i] - __bfloat162float(hi[i]));
    }
    __nv_bfloat162 ph0 = {hi[0], hi[1]}, ph1 = {hi[2], hi[3]};
    __nv_bfloat162 pl0 = {lo[0], lo[1]}, pl1 = {lo[2], lo[3]};
    uint2 uh, ul;
    uh.x = *(uint32_t*)&ph0; uh.y = *(uint32_t*)&ph1;
    ul.x = *(uint32_t*)&pl0; ul.y = *(uint32_t*)&pl1;
    ((uint2*)g_mean_hi)[(size_t)sgi * (H_ / 4) + col] = uh;
    ((uint2*)g_mean_lo)[(size_t)sgi * (H_ / 4) + col] = ul;

    // self-clean for next replay
    float4 z = {0, 0, 0, 0};
    *sp = z;
    if (col == 0) g_cnt[sgi] = 0u;
}

// ---------------------------------------------------------------------------
// Kernel 2: bf16x3 warp-MMA GEMM + bias + SELU + partial logits + fused
// deterministic softmax finish.  (R13-proven, unchanged.)
// CTA tile 64x96, block = 128 (4 warps: 2M x 2N, warp tile 32x48).
// KC=64, 3-stage cp.async ring, wait_group 1.  grid = (8,16) = 128 CTAs.
// ---------------------------------------------------------------------------
#define TM 64
#define TN 96
#define KC 64
#define KPAD 72
#define NSTAGE 3
#define NCHUNK (H_ / KC)   // 12
#define A_STAGE (TM * KPAD)
#define B_STAGE (TN * KPAD)
#define SMEM_BYTES (NSTAGE * (2 * A_STAGE + 2 * B_STAGE) * 2 + \
                    TN * C_ * 4 + TN * 4)   // 140544

__global__ __launch_bounds__(128) void gemm_fused_kernel(
    const float* __restrict__ bias, const float* __restrict__ Wo,
    const float* __restrict__ bo, float* __restrict__ out) {
    extern __shared__ __align__(16) char dynsmem[];
    __nv_bfloat16* sA_hi = (__nv_bfloat16*)dynsmem;       // [NSTAGE][TM][KPAD]
    __nv_bfloat16* sA_lo = sA_hi + NSTAGE * A_STAGE;
    __nv_bfloat16* sB_hi = sA_lo + NSTAGE * A_STAGE;      // [NSTAGE][TN][KPAD]
    __nv_bfloat16* sB_lo = sB_hi + NSTAGE * B_STAGE;
    float* sWo   = (float*)(sB_lo + NSTAGE * B_STAGE);
    float* sBias = sWo + TN * C_;
    __shared__ int s_last;

    const int tid  = threadIdx.x;
    const int wid  = tid >> 5;
    const int lane = tid & 31;
    const int warp_m = wid & 1;
    const int warp_n = wid >> 1;
    const int n0 = blockIdx.x * TN;
    const int m0 = blockIdx.y * TM;

    for (int i = tid; i < TN * C_; i += 128) sWo[i] = Wo[(size_t)n0 * C_ + i];
    if (tid < TN) sBias[tid] = bias[n0 + tid];

    const __nv_bfloat16* __restrict__ Ahi = g_mean_hi + (size_t)m0 * H_;
    const __nv_bfloat16* __restrict__ Alo = g_mean_lo + (size_t)m0 * H_;
    const __nv_bfloat16* __restrict__ Bhi = g_wt_hi + (size_t)n0 * H_;
    const __nv_bfloat16* __restrict__ Blo = g_wt_lo + (size_t)n0 * H_;

    auto issue = [&](int ck) {
        const int st = ck % NSTAGE;
        const int k0 = ck * KC;
        #pragma unroll
        for (int i = 0; i < 4; ++i) {
            const int unit = tid + i * 128;
            const int row = unit >> 3, u = unit & 7;
            const size_t goff = (size_t)row * H_ + k0 + u * 8;
            const int soff = (st * TM + row) * KPAD + u * 8;
            CP16(s2u(sA_hi + soff), Ahi + goff);
            CP16(s2u(sA_lo + soff), Alo + goff);
        }
        #pragma unroll
        for (int i = 0; i < 6; ++i) {
            const int unit = tid + i * 128;
            const int row = unit >> 3, u = unit & 7;
            const size_t goff = (size_t)row * H_ + k0 + u * 8;
            const int soff = (st * TN + row) * KPAD + u * 8;
            CP16(s2u(sB_hi + soff), Bhi + goff);
            CP16(s2u(sB_lo + soff), Blo + goff);
        }
    };

    issue(0); CP_COMMIT();
    issue(1); CP_COMMIT();

    float acc[2][6][4] = {};

    #pragma unroll 1
    for (int ck = 0; ck < NCHUNK; ++ck) {
        if (ck + 2 < NCHUNK) {
            asm volatile("cp.async.wait_group 1;" ::: "memory");
        } else {
            asm volatile("cp.async.wait_group 0;" ::: "memory");
        }
        __syncthreads();
        if (ck + 2 < NCHUNK) { issue(ck + 2); CP_COMMIT(); }

        const int abase = (ck % NSTAGE) * A_STAGE;
        const int bbase = (ck % NSTAGE) * B_STAGE;
        #pragma unroll
        for (int ks = 0; ks < KC / 16; ++ks) {
            const int kw = ks * 16;
            uint32_t ah[2][4], al[2][4], bh[3][4], bl[3][4];
            #pragma unroll
            for (int mt = 0; mt < 2; ++mt) {
                int row = warp_m * 32 + mt * 16 + (lane & 15);
                int col = kw + ((lane >> 4) << 3);
                ldsm_x4(ah[mt], s2u(sA_hi + abase + row * KPAD + col));
                ldsm_x4(al[mt], s2u(sA_lo + abase + row * KPAD + col));
            }
            #pragma unroll
            for (int np = 0; np < 3; ++np) {
                int row = warp_n * 48 + np * 16 + (lane & 7) +
                          ((lane >> 4) << 3);
                int col = kw + (((lane >> 3) & 1) << 3);
                ldsm_x4(bh[np], s2u(sB_hi + bbase + row * KPAD + col));
                ldsm_x4(bl[np], s2u(sB_lo + bbase + row * KPAD + col));
            }
            #pragma unroll
            for (int mt = 0; mt < 2; ++mt) {
                #pragma unroll
                for (int nt = 0; nt < 6; ++nt) {
                    const uint32_t* bhp = &bh[nt >> 1][(nt & 1) * 2];
                    const uint32_t* blp = &bl[nt >> 1][(nt & 1) * 2];
                    mma_bf16(acc[mt][nt], ah[mt], bhp);
                    mma_bf16(acc[mt][nt], ah[mt], blp);
                    mma_bf16(acc[mt][nt], al[mt], bhp);
                }
            }
        }
    }

    // ---- epilogue: bias + SELU + partial logits ----
    const float kScale = 1.0507009873554805f;
    const float kAlpha = 1.6732632423543772f;
    float pl[4][C_] = {};
    #pragma unroll
    for (int mt = 0; mt < 2; ++mt) {
        #pragma unroll
        for (int nt = 0; nt < 6; ++nt) {
            #pragma unroll
            for (int e = 0; e < 4; ++e) {
                int col = warp_n * 48 + nt * 8 + (lane & 3) * 2 + (e & 1);
                float x = acc[mt][nt][e] + sBias[col];
                float y = (x > 0.0f) ? x : kAlpha * expm1f(x);
                float h = kScale * y;
                int ridx = mt * 2 + (e >> 1);
                #pragma unroll
                for (int c = 0; c < C_; ++c)
                    pl[ridx][c] = fmaf(h, sWo[col * C_ + c], pl[ridx][c]);
            }
        }
    }
    #pragma unroll
    for (int ridx = 0; ridx < 4; ++ridx)
        #pragma unroll
        for (int c = 0; c < C_; ++c) {
            pl[ridx][c] += __shfl_xor_sync(0xFFFFFFFFu, pl[ridx][c], 1);
            pl[ridx][c] += __shfl_xor_sync(0xFFFFFFFFu, pl[ridx][c], 2);
        }
    if ((lane & 3) == 0) {
        const int slot = blockIdx.x * 2 + warp_n;
        #pragma unroll
        for (int ridx = 0; ridx < 4; ++ridx) {
            int row = m0 + warp_m * 32 + (ridx >> 1) * 16 + (lane >> 2) +
                      (ridx & 1) * 8;
            float* dst = g_partial + ((size_t)slot * NSEG + row) * C_;
            #pragma unroll
            for (int c = 0; c < C_; ++c) dst[c] = pl[ridx][c];
        }
    }

    // ---- fused finish: last CTA per M-tile reduces + softmax ----
    __threadfence();
    __syncthreads();
    if (tid == 0) {
        unsigned int old = atomicAdd(&g_arrive[blockIdx.y], 1u);
        s_last = (old == NTILE_N - 1) ? 1 : 0;
    }
    __syncthreads();
    if (s_last) {
        __threadfence();
        if (tid < TM) {
            const int row = m0 + tid;
            float l[C_];
            #pragma unroll
            for (int c = 0; c < C_; ++c) l[c] = bo[c];
            #pragma unroll
            for (int t = 0; t < NTILE_P; ++t) {
                const float* p = g_partial + ((size_t)t * NSEG + row) * C_;
                #pragma unroll
                for (int c = 0; c < C_; ++c) l[c] += p[c];
            }
            float mx = -INFINITY;
            #pragma unroll
            for (int c = 0; c < C_; ++c) mx = fmaxf(mx, l[c]);
            float sum = 0.0f;
            #pragma unroll
            for (int c = 0; c < C_; ++c) { l[c] = expf(l[c] - mx); sum += l[c]; }
            float inv = 1.0f / sum;
            #pragma unroll
            for (int c = 0; c < C_; ++c)
                out[(size_t)row * C_ + c] = l[c] * inv;
        }
        __syncthreads();
        if (tid == 0) g_arrive[blockIdx.y] = 0u;   // self-reset for replay
    }
}

// ---------------------------------------------------------------------------
// Launch
// ---------------------------------------------------------------------------
extern "C" void kernel_launch(void* const* d_in, const int* in_sizes, int n_in,
                              void* d_out, int out_size) {
    const float* hidden = (const float*)d_in[0];
    const int*   seg    = (const int*)d_in[1];
    int base = (n_in >= 7) ? 3 : 2;
    const float* W_h = (const float*)d_in[base + 0];
    const float* b_h = (const float*)d_in[base + 1];
    const float* W_o = (const float*)d_in[base + 2];
    const float* b_o = (const float*)d_in[base + 3];
    float* out = (float*)d_out;

    cudaFuncSetAttribute(gemm_fused_kernel,
                         cudaFuncAttributeMaxDynamicSharedMemorySize,
                         SMEM_BYTES);

    prep1_kernel<<<NCHKBLK + NWPREP, 384>>>(hidden, seg, W_h);
    prep2_kernel<<<NSEG, 192>>>();

    dim3 gg(NTILE_N, NTILE_M);   // (8, 16) = 128 CTAs
    gemm_fused_kernel<<<gg, 128, SMEM_BYTES>>>(b_h, W_o, b_o, out);
}

// round 15
// speedup vs baseline: 1.1471x; 1.1471x over previous
#include <cuda_runtime.h>
#include <cuda_bf16.h>
#include <math.h>
#include <stdint.h>

// Problem constants (fixed-shape problem)
#define B_  64
#define S_  512
#define H_  768
#define U_  16
#define C_  5
#define NSEG (B_ * U_)       // 1024
#define NTILE_N 8            // 768 / 96
#define NTILE_M 16           // 1024 / 64
#define NTILE_P (NTILE_N * 2)  // 16 partial slots (48-col warp slices)
#define NWPREP  576          // 24 x 24 transpose blocks

// ---------------------------------------------------------------------------
// Scratch (no allocation allowed)
// ---------------------------------------------------------------------------
__device__ __align__(16) __nv_bfloat16 g_mean_hi[NSEG * H_];
__device__ __align__(16) __nv_bfloat16 g_mean_lo[NSEG * H_];
__device__ __align__(16) __nv_bfloat16 g_wt_hi[H_ * H_];   // W_h^T: [n][k]
__device__ __align__(16) __nv_bfloat16 g_wt_lo[H_ * H_];
__device__ float g_partial[NTILE_P * NSEG * C_];
__device__ unsigned int g_arrive[NTILE_M];   // zero-init; self-resetting

// ---------------------------------------------------------------------------
// PTX helpers (baseline PTX only — compiles for compute_103)
// ---------------------------------------------------------------------------
__device__ __forceinline__ void mma_bf16(float* c, const uint32_t* a,
                                         const uint32_t* b) {
    asm volatile(
        "mma.sync.aligned.m16n8k16.row.col.f32.bf16.bf16.f32 "
        "{%0,%1,%2,%3}, {%4,%5,%6,%7}, {%8,%9}, {%0,%1,%2,%3};\n"
        : "+f"(c[0]), "+f"(c[1]), "+f"(c[2]), "+f"(c[3])
        : "r"(a[0]), "r"(a[1]), "r"(a[2]), "r"(a[3]), "r"(b[0]), "r"(b[1]));
}
__device__ __forceinline__ void ldsm_x4(uint32_t* r, uint32_t addr) {
    asm volatile(
        "ldmatrix.sync.aligned.m8n8.x4.shared.b16 {%0,%1,%2,%3}, [%4];"
        : "=r"(r[0]), "=r"(r[1]), "=r"(r[2]), "=r"(r[3]) : "r"(addr));
}
#define CP16(dst, src) \
    asm volatile("cp.async.cg.shared.global [%0], [%1], 16;" \
                 :: "r"(dst), "l"(src))
#define CP_COMMIT() asm volatile("cp.async.commit_group;" ::: "memory")
__device__ __forceinline__ uint32_t s2u(const void* p) {
    return (uint32_t)__cvta_generic_to_shared(p);
}

// ---------------------------------------------------------------------------
// Kernel 1 (merged prep), block = 384 — exact round-9/13 proven version.
// ---------------------------------------------------------------------------
__global__ __launch_bounds__(384) void prep_kernel(
    const float* __restrict__ hidden, const int* __restrict__ seg,
    const float* __restrict__ W) {
    const int bid = blockIdx.x;
    const int tid = threadIdx.x;

    if (bid < NSEG) {
        __shared__ int s_lt, s_eq;
        __shared__ float4 red[192];
        const int b = bid >> 4, u = bid & 15;
        if (tid == 0) { s_lt = 0; s_eq = 0; }
        __syncthreads();
        if (tid < 128) {
            int4 v = ((const int4*)(seg + (size_t)b * S_))[tid];
            int lt = (v.x < u) + (v.y < u) + (v.z < u) + (v.w < u);
            int eq = (v.x == u) + (v.y == u) + (v.z == u) + (v.w == u);
            #pragma unroll
            for (int off = 16; off > 0; off >>= 1) {
                lt += __shfl_xor_sync(0xFFFFFFFFu, lt, off);
                eq += __shfl_xor_sync(0xFFFFFFFFu, eq, off);
            }
            if ((tid & 31) == 0) { atomicAdd(&s_lt, lt); atomicAdd(&s_eq, eq); }
        }
        __syncthreads();
        const int start = b * S_ + s_lt;
        const int cnt   = s_eq;
        const float inv = 1.0f / fmaxf((float)cnt, 1.0f);

        const int gcol = tid % 192;
        const int grp  = tid / 192;
        const float4* __restrict__ hp =
            (const float4*)hidden + (size_t)start * (H_ / 4) + gcol;

        float4 a0 = {0,0,0,0}, a1 = {0,0,0,0}, a2 = {0,0,0,0}, a3 = {0,0,0,0};
        int r = grp;
        for (; r + 6 < cnt; r += 8) {
            float4 v0 = hp[(size_t)(r + 0) * (H_ / 4)];
            float4 v1 = hp[(size_t)(r + 2) * (H_ / 4)];
            float4 v2 = hp[(size_t)(r + 4) * (H_ / 4)];
            float4 v3 = hp[(size_t)(r + 6) * (H_ / 4)];
            a0.x += v0.x; a0.y += v0.y; a0.z += v0.z; a0.w += v0.w;
            a1.x += v1.x; a1.y += v1.y; a1.z += v1.z; a1.w += v1.w;
            a2.x += v2.x; a2.y += v2.y; a2.z += v2.z; a2.w += v2.w;
            a3.x += v3.x; a3.y += v3.y; a3.z += v3.z; a3.w += v3.w;
        }
        for (; r < cnt; r += 2) {
            float4 v0 = hp[(size_t)r * (H_ / 4)];
            a0.x += v0.x; a0.y += v0.y; a0.z += v0.z; a0.w += v0.w;
        }
        a0.x = (a0.x + a1.x) + (a2.x + a3.x);
        a0.y = (a0.y + a1.y) + (a2.y + a3.y);
        a0.z = (a0.z + a1.z) + (a2.z + a3.z);
        a0.w = (a0.w + a1.w) + (a2.w + a3.w);

        if (grp == 1) red[gcol] = a0;
        __syncthreads();
        if (grp == 0) {
            float4 p = red[gcol];
            float m[4];
            m[0] = (a0.x + p.x) * inv;
            m[1] = (a0.y + p.y) * inv;
            m[2] = (a0.z + p.z) * inv;
            m[3] = (a0.w + p.w) * inv;

            __nv_bfloat16 hi[4], lo[4];
            #pragma unroll
            for (int i = 0; i < 4; ++i) {
                hi[i] = __float2bfloat16(m[i]);
                lo[i] = __float2bfloat16(m[i] - __bfloat162float(hi[i]));
            }
            __nv_bfloat162 ph0 = {hi[0], hi[1]}, ph1 = {hi[2], hi[3]};
            __nv_bfloat162 pl0 = {lo[0], lo[1]}, pl1 = {lo[2], lo[3]};
            uint2 uh, ul;
            uh.x = *(uint32_t*)&ph0; uh.y = *(uint32_t*)&ph1;
            ul.x = *(uint32_t*)&pl0; ul.y = *(uint32_t*)&pl1;
            ((uint2*)g_mean_hi)[(size_t)bid * (H_ / 4) + gcol] = uh;
            ((uint2*)g_mean_lo)[(size_t)bid * (H_ / 4) + gcol] = ul;
        }
    } else {
        __shared__ float t[32][33];
        const int w  = bid - NSEG;
        const int n0 = (w % 24) * 32, k0 = (w / 24) * 32;
        if (tid < 256) {
            const int tx = tid & 31, ty = tid >> 5;
            #pragma unroll
            for (int r = 0; r < 32; r += 8)
                t[ty + r][tx] = W[(size_t)(k0 + ty + r) * H_ + n0 + tx];
        }
        __syncthreads();
        if (tid < 256) {
            const int tx = tid & 31, ty = tid >> 5;
            const int k = k0 + tx;
            #pragma unroll
            for (int r = 0; r < 32; r += 8) {
                const int n = n0 + ty + r;
                float v = t[tx][ty + r];
                __nv_bfloat16 hi = __float2bfloat16(v);
                __nv_bfloat16 lo = __float2bfloat16(v - __bfloat162float(hi));
                g_wt_hi[(size_t)n * H_ + k] = hi;
                g_wt_lo[(size_t)n * H_ + k] = lo;
            }
        }
    }
}

// ---------------------------------------------------------------------------
// Kernel 2: bf16x3 warp-MMA GEMM + bias + SELU + partial logits + fused
// deterministic softmax finish.  (R13 config, ring deepened 3 -> 4 stages.)
// CTA tile 64x96, block = 128 (4 warps: 2M x 2N, warp tile 32x48).
// KC=64, 4-stage cp.async ring, wait_group 2 (prefetch depth 3).
// grid = (8, 16) = 128 CTAs -> exactly 1 CTA/SM.
// ---------------------------------------------------------------------------
#define TM 64
#define TN 96
#define KC 64
#define KPAD 72
#define NSTAGE 4
#define NCHUNK (H_ / KC)   // 12
#define A_STAGE (TM * KPAD)                 // 4608 elems
#define B_STAGE (TN * KPAD)                 // 6912 elems
#define SMEM_BYTES (NSTAGE * (2 * A_STAGE + 2 * B_STAGE) * 2 + \
                    TN * C_ * 4 + TN * 4)   // 186624

__global__ __launch_bounds__(128) void gemm_fused_kernel(
    const float* __restrict__ bias, const float* __restrict__ Wo,
    const float* __restrict__ bo, float* __restrict__ out) {
    extern __shared__ __align__(16) char dynsmem[];
    __nv_bfloat16* sA_hi = (__nv_bfloat16*)dynsmem;       // [NSTAGE][TM][KPAD]
    __nv_bfloat16* sA_lo = sA_hi + NSTAGE * A_STAGE;
    __nv_bfloat16* sB_hi = sA_lo + NSTAGE * A_STAGE;      // [NSTAGE][TN][KPAD]
    __nv_bfloat16* sB_lo = sB_hi + NSTAGE * B_STAGE;
    float* sWo   = (float*)(sB_lo + NSTAGE * B_STAGE);
    float* sBias = sWo + TN * C_;
    __shared__ int s_last;

    const int tid  = threadIdx.x;
    const int wid  = tid >> 5;
    const int lane = tid & 31;
    const int warp_m = wid & 1;
    const int warp_n = wid >> 1;
    const int n0 = blockIdx.x * TN;
    const int m0 = blockIdx.y * TM;

    for (int i = tid; i < TN * C_; i += 128) sWo[i] = Wo[(size_t)n0 * C_ + i];
    if (tid < TN) sBias[tid] = bias[n0 + tid];

    const __nv_bfloat16* __restrict__ Ahi = g_mean_hi + (size_t)m0 * H_;
    const __nv_bfloat16* __restrict__ Alo = g_mean_lo + (size_t)m0 * H_;
    const __nv_bfloat16* __restrict__ Bhi = g_wt_hi + (size_t)n0 * H_;
    const __nv_bfloat16* __restrict__ Blo = g_wt_lo + (size_t)n0 * H_;

    // copy one chunk into stage ck % NSTAGE
    auto issue = [&](int ck) {
        const int st = ck % NSTAGE;
        const int k0 = ck * KC;
        #pragma unroll
        for (int i = 0; i < 4; ++i) {
            const int unit = tid + i * 128;          // 0..511
            const int row = unit >> 3, u = unit & 7;
            const size_t goff = (size_t)row * H_ + k0 + u * 8;
            const int soff = (st * TM + row) * KPAD + u * 8;
            CP16(s2u(sA_hi + soff), Ahi + goff);
            CP16(s2u(sA_lo + soff), Alo + goff);
        }
        #pragma unroll
        for (int i = 0; i < 6; ++i) {
            const int unit = tid + i * 128;          // 0..767
            const int row = unit >> 3, u = unit & 7;
            const size_t goff = (size_t)row * H_ + k0 + u * 8;
            const int soff = (st * TN + row) * KPAD + u * 8;
            CP16(s2u(sB_hi + soff), Bhi + goff);
            CP16(s2u(sB_lo + soff), Blo + goff);
        }
    };

    issue(0); CP_COMMIT();
    issue(1); CP_COMMIT();
    issue(2); CP_COMMIT();

    float acc[2][6][4] = {};

    #pragma unroll 1
    for (int ck = 0; ck < NCHUNK; ++ck) {
        // chunk ck was issued >= 3 iterations ago -> wait is near-free
        if (ck + 3 < NCHUNK) {
            asm volatile("cp.async.wait_group 2;" ::: "memory");
        } else {
            asm volatile("cp.async.wait_group 0;" ::: "memory");
        }
        __syncthreads();
        if (ck + 3 < NCHUNK) { issue(ck + 3); CP_COMMIT(); }

        const int abase = (ck % NSTAGE) * A_STAGE;
        const int bbase = (ck % NSTAGE) * B_STAGE;
        #pragma unroll
        for (int ks = 0; ks < KC / 16; ++ks) {
            const int kw = ks * 16;
            uint32_t ah[2][4], al[2][4], bh[3][4], bl[3][4];
            #pragma unroll
            for (int mt = 0; mt < 2; ++mt) {
                int row = warp_m * 32 + mt * 16 + (lane & 15);
                int col = kw + ((lane >> 4) << 3);
                ldsm_x4(ah[mt], s2u(sA_hi + abase + row * KPAD + col));
                ldsm_x4(al[mt], s2u(sA_lo + abase + row * KPAD + col));
            }
            #pragma unroll
            for (int np = 0; np < 3; ++np) {
                int row = warp_n * 48 + np * 16 + (lane & 7) +
                          ((lane >> 4) << 3);
                int col = kw + (((lane >> 3) & 1) << 3);
                ldsm_x4(bh[np], s2u(sB_hi + bbase + row * KPAD + col));
                ldsm_x4(bl[np], s2u(sB_lo + bbase + row * KPAD + col));
            }
            #pragma unroll
            for (int mt = 0; mt < 2; ++mt) {
                #pragma unroll
                for (int nt = 0; nt < 6; ++nt) {
                    const uint32_t* bhp = &bh[nt >> 1][(nt & 1) * 2];
                    const uint32_t* blp = &bl[nt >> 1][(nt & 1) * 2];
                    mma_bf16(acc[mt][nt], ah[mt], bhp);
                    mma_bf16(acc[mt][nt], ah[mt], blp);
                    mma_bf16(acc[mt][nt], al[mt], bhp);
                }
            }
        }
    }

    // ---- epilogue: bias + SELU + partial logits ----
    const float kScale = 1.0507009873554805f;
    const float kAlpha = 1.6732632423543772f;
    float pl[4][C_] = {};
    #pragma unroll
    for (int mt = 0; mt < 2; ++mt) {
        #pragma unroll
        for (int nt = 0; nt < 6; ++nt) {
            #pragma unroll
            for (int e = 0; e < 4; ++e) {
                int col = warp_n * 48 + nt * 8 + (lane & 3) * 2 + (e & 1);
                float x = acc[mt][nt][e] + sBias[col];
                float y = (x > 0.0f) ? x : kAlpha * expm1f(x);
                float h = kScale * y;
                int ridx = mt * 2 + (e >> 1);
                #pragma unroll
                for (int c = 0; c < C_; ++c)
                    pl[ridx][c] = fmaf(h, sWo[col * C_ + c], pl[ridx][c]);
            }
        }
    }
    #pragma unroll
    for (int ridx = 0; ridx < 4; ++ridx)
        #pragma unroll
        for (int c = 0; c < C_; ++c) {
            pl[ridx][c] += __shfl_xor_sync(0xFFFFFFFFu, pl[ridx][c], 1);
            pl[ridx][c] += __shfl_xor_sync(0xFFFFFFFFu, pl[ridx][c], 2);
        }
    if ((lane & 3) == 0) {
        const int slot = blockIdx.x * 2 + warp_n;
        #pragma unroll
        for (int ridx = 0; ridx < 4; ++ridx) {
            int row = m0 + warp_m * 32 + (ridx >> 1) * 16 + (lane >> 2) +
                      (ridx & 1) * 8;
            float* dst = g_partial + ((size_t)slot * NSEG + row) * C_;
            #pragma unroll
            for (int c = 0; c < C_; ++c) dst[c] = pl[ridx][c];
        }
    }

    // ---- fused finish: last CTA per M-tile reduces + softmax ----
    __threadfence();     // make this CTA's partial writes globally visible
    __syncthreads();
    if (tid == 0) {
        unsigned int old = atomicAdd(&g_arrive[blockIdx.y], 1u);
        s_last = (old == NTILE_N - 1) ? 1 : 0;
    }
    __syncthreads();
    if (s_last) {
        __threadfence();   // acquire: see all other CTAs' partials
        if (tid < TM) {
            const int row = m0 + tid;
            float l[C_];
            #pragma unroll
            for (int c = 0; c < C_; ++c) l[c] = bo[c];
            #pragma unroll
            for (int t = 0; t < NTILE_P; ++t) {
                const float* p = g_partial + ((size_t)t * NSEG + row) * C_;
                #pragma unroll
                for (int c = 0; c < C_; ++c) l[c] += p[c];
            }
            float mx = -INFINITY;
            #pragma unroll
            for (int c = 0; c < C_; ++c) mx = fmaxf(mx, l[c]);
            float sum = 0.0f;
            #pragma unroll
            for (int c = 0; c < C_; ++c) { l[c] = expf(l[c] - mx); sum += l[c]; }
            float inv = 1.0f / sum;
            #pragma unroll
            for (int c = 0; c < C_; ++c)
                out[(size_t)row * C_ + c] = l[c] * inv;
        }
        __syncthreads();
        if (tid == 0) g_arrive[blockIdx.y] = 0u;   // self-reset for replay
    }
}

// ---------------------------------------------------------------------------
// Launch
// ---------------------------------------------------------------------------
extern "C" void kernel_launch(void* const* d_in, const int* in_sizes, int n_in,
                              void* d_out, int out_size) {
    const float* hidden = (const float*)d_in[0];
    const int*   seg    = (const int*)d_in[1];
    int base = (n_in >= 7) ? 3 : 2;
    const float* W_h = (const float*)d_in[base + 0];
    const float* b_h = (const float*)d_in[base + 1];
    const float* W_o = (const float*)d_in[base + 2];
    const float* b_o = (const float*)d_in[base + 3];
    float* out = (float*)d_out;

    cudaFuncSetAttribute(gemm_fused_kernel,
                         cudaFuncAttributeMaxDynamicSharedMemorySize,
                         SMEM_BYTES);

    prep_kernel<<<NSEG + NWPREP, 384>>>(hidden, seg, W_h);

    dim3 gg(NTILE_N, NTILE_M);   // (8, 16) = 128 CTAs
    gemm_fused_kernel<<<gg, 128, SMEM_BYTES>>>(b_h, W_o, b_o, out);
}

// round 16
// speedup vs baseline: 1.1479x; 1.0007x over previous
#include <cuda_runtime.h>
#include <cuda_bf16.h>
#include <math.h>
#include <stdint.h>

// Problem constants (fixed-shape problem)
#define B_  64
#define S_  512
#define H_  768
#define U_  16
#define C_  5
#define NSEG (B_ * U_)       // 1024
#define NTILE_N 8            // 768 / 96
#define NTILE_M 16           // 1024 / 64
#define NTILE_P (NTILE_N * 2)  // 16 partial slots (48-col warp slices)
#define NWPREP  576          // 24 x 24 transpose blocks

// ---------------------------------------------------------------------------
// Scratch (no allocation allowed)
// ---------------------------------------------------------------------------
__device__ __align__(16) __nv_bfloat16 g_mean_hi[NSEG * H_];
__device__ __align__(16) __nv_bfloat16 g_mean_lo[NSEG * H_];
__device__ __align__(16) __nv_bfloat16 g_wt_hi[H_ * H_];   // W_h^T: [n][k]
__device__ __align__(16) __nv_bfloat16 g_wt_lo[H_ * H_];
__device__ float g_partial[NTILE_P * NSEG * C_];
__device__ unsigned int g_arrive[NTILE_M];   // zero-init; self-resetting

// ---------------------------------------------------------------------------
// PTX helpers (baseline PTX only — compiles for compute_103)
// ---------------------------------------------------------------------------
__device__ __forceinline__ void mma_bf16(float* c, const uint32_t* a,
                                         const uint32_t* b) {
    asm volatile(
        "mma.sync.aligned.m16n8k16.row.col.f32.bf16.bf16.f32 "
        "{%0,%1,%2,%3}, {%4,%5,%6,%7}, {%8,%9}, {%0,%1,%2,%3};\n"
        : "+f"(c[0]), "+f"(c[1]), "+f"(c[2]), "+f"(c[3])
        : "r"(a[0]), "r"(a[1]), "r"(a[2]), "r"(a[3]), "r"(b[0]), "r"(b[1]));
}
__device__ __forceinline__ void ldsm_x4(uint32_t* r, uint32_t addr) {
    asm volatile(
        "ldmatrix.sync.aligned.m8n8.x4.shared.b16 {%0,%1,%2,%3}, [%4];"
        : "=r"(r[0]), "=r"(r[1]), "=r"(r[2]), "=r"(r[3]) : "r"(addr));
}
#define CP16(dst, src) \
    asm volatile("cp.async.cg.shared.global [%0], [%1], 16;" \
                 :: "r"(dst), "l"(src))
#define CP_COMMIT() asm volatile("cp.async.commit_group;" ::: "memory")
__device__ __forceinline__ uint32_t s2u(const void* p) {
    return (uint32_t)__cvta_generic_to_shared(p);
}

// ---------------------------------------------------------------------------
// Kernel 1 (merged prep), block = 384 — exact round-9/13 proven version.
// ---------------------------------------------------------------------------
__global__ __launch_bounds__(384) void prep_kernel(
    const float* __restrict__ hidden, const int* __restrict__ seg,
    const float* __restrict__ W) {
    const int bid = blockIdx.x;
    const int tid = threadIdx.x;

    if (bid < NSEG) {
        __shared__ int s_lt, s_eq;
        __shared__ float4 red[192];
        const int b = bid >> 4, u = bid & 15;
        if (tid == 0) { s_lt = 0; s_eq = 0; }
        __syncthreads();
        if (tid < 128) {
            int4 v = ((const int4*)(seg + (size_t)b * S_))[tid];
            int lt = (v.x < u) + (v.y < u) + (v.z < u) + (v.w < u);
            int eq = (v.x == u) + (v.y == u) + (v.z == u) + (v.w == u);
            #pragma unroll
            for (int off = 16; off > 0; off >>= 1) {
                lt += __shfl_xor_sync(0xFFFFFFFFu, lt, off);
                eq += __shfl_xor_sync(0xFFFFFFFFu, eq, off);
            }
            if ((tid & 31) == 0) { atomicAdd(&s_lt, lt); atomicAdd(&s_eq, eq); }
        }
        __syncthreads();
        const int start = b * S_ + s_lt;
        const int cnt   = s_eq;
        const float inv = 1.0f / fmaxf((float)cnt, 1.0f);

        const int gcol = tid % 192;
        const int grp  = tid / 192;
        const float4* __restrict__ hp =
            (const float4*)hidden + (size_t)start * (H_ / 4) + gcol;

        float4 a0 = {0,0,0,0}, a1 = {0,0,0,0}, a2 = {0,0,0,0}, a3 = {0,0,0,0};
        int r = grp;
        for (; r + 6 < cnt; r += 8) {
            float4 v0 = hp[(size_t)(r + 0) * (H_ / 4)];
            float4 v1 = hp[(size_t)(r + 2) * (H_ / 4)];
            float4 v2 = hp[(size_t)(r + 4) * (H_ / 4)];
            float4 v3 = hp[(size_t)(r + 6) * (H_ / 4)];
            a0.x += v0.x; a0.y += v0.y; a0.z += v0.z; a0.w += v0.w;
            a1.x += v1.x; a1.y += v1.y; a1.z += v1.z; a1.w += v1.w;
            a2.x += v2.x; a2.y += v2.y; a2.z += v2.z; a2.w += v2.w;
            a3.x += v3.x; a3.y += v3.y; a3.z += v3.z; a3.w += v3.w;
        }
        for (; r < cnt; r += 2) {
            float4 v0 = hp[(size_t)r * (H_ / 4)];
            a0.x += v0.x; a0.y += v0.y; a0.z += v0.z; a0.w += v0.w;
        }
        a0.x = (a0.x + a1.x) + (a2.x + a3.x);
        a0.y = (a0.y + a1.y) + (a2.y + a3.y);
        a0.z = (a0.z + a1.z) + (a2.z + a3.z);
        a0.w = (a0.w + a1.w) + (a2.w + a3.w);

        if (grp == 1) red[gcol] = a0;
        __syncthreads();
        if (grp == 0) {
            float4 p = red[gcol];
            float m[4];
            m[0] = (a0.x + p.x) * inv;
            m[1] = (a0.y + p.y) * inv;
            m[2] = (a0.z + p.z) * inv;
            m[3] = (a0.w + p.w) * inv;

            __nv_bfloat16 hi[4], lo[4];
            #pragma unroll
            for (int i = 0; i < 4; ++i) {
                hi[i] = __float2bfloat16(m[i]);
                lo[i] = __float2bfloat16(m[i] - __bfloat162float(hi[i]));
            }
            __nv_bfloat162 ph0 = {hi[0], hi[1]}, ph1 = {hi[2], hi[3]};
            __nv_bfloat162 pl0 = {lo[0], lo[1]}, pl1 = {lo[2], lo[3]};
            uint2 uh, ul;
            uh.x = *(uint32_t*)&ph0; uh.y = *(uint32_t*)&ph1;
            ul.x = *(uint32_t*)&pl0; ul.y = *(uint32_t*)&pl1;
            ((uint2*)g_mean_hi)[(size_t)bid * (H_ / 4) + gcol] = uh;
            ((uint2*)g_mean_lo)[(size_t)bid * (H_ / 4) + gcol] = ul;
        }
    } else {
        __shared__ float t[32][33];
        const int w  = bid - NSEG;
        const int n0 = (w % 24) * 32, k0 = (w / 24) * 32;
        if (tid < 256) {
            const int tx = tid & 31, ty = tid >> 5;
            #pragma unroll
            for (int r = 0; r < 32; r += 8)
                t[ty + r][tx] = W[(size_t)(k0 + ty + r) * H_ + n0 + tx];
        }
        __syncthreads();
        if (tid < 256) {
            const int tx = tid & 31, ty = tid >> 5;
            const int k = k0 + tx;
            #pragma unroll
            for (int r = 0; r < 32; r += 8) {
                const int n = n0 + ty + r;
                float v = t[tx][ty + r];
                __nv_bfloat16 hi = __float2bfloat16(v);
                __nv_bfloat16 lo = __float2bfloat16(v - __bfloat162float(hi));
                g_wt_hi[(size_t)n * H_ + k] = hi;
                g_wt_lo[(size_t)n * H_ + k] = lo;
            }
        }
    }
}

// ---------------------------------------------------------------------------
// Kernel 2: bf16x3 warp-MMA GEMM + bias + SELU + partial logits + fused
// deterministic softmax finish.
// CTA tile 64x96, block = 128 (4 warps: 2M x 2N, warp tile 32x48).
// KC=64, 4-stage cp.async ring, wait_group 2.
// MMA issue order is PRODUCT-MAJOR: all 12 AhiBhi, then 12 AhiBlo, then 12
// AloBhi — consecutive MMAs hit different accumulators, so the single warp
// per SMSP is no longer serialized on the accumulator RAW chain.
// grid = (8, 16) = 128 CTAs -> exactly 1 CTA/SM.
// ---------------------------------------------------------------------------
#define TM 64
#define TN 96
#define KC 64
#define KPAD 72
#define NSTAGE 4
#define NCHUNK (H_ / KC)   // 12
#define A_STAGE (TM * KPAD)                 // 4608 elems
#define B_STAGE (TN * KPAD)                 // 6912 elems
#define SMEM_BYTES (NSTAGE * (2 * A_STAGE + 2 * B_STAGE) * 2 + \
                    TN * C_ * 4 + TN * 4)   // 186624

__global__ __launch_bounds__(128) void gemm_fused_kernel(
    const float* __restrict__ bias, const float* __restrict__ Wo,
    const float* __restrict__ bo, float* __restrict__ out) {
    extern __shared__ __align__(16) char dynsmem[];
    __nv_bfloat16* sA_hi = (__nv_bfloat16*)dynsmem;       // [NSTAGE][TM][KPAD]
    __nv_bfloat16* sA_lo = sA_hi + NSTAGE * A_STAGE;
    __nv_bfloat16* sB_hi = sA_lo + NSTAGE * A_STAGE;      // [NSTAGE][TN][KPAD]
    __nv_bfloat16* sB_lo = sB_hi + NSTAGE * B_STAGE;
    float* sWo   = (float*)(sB_lo + NSTAGE * B_STAGE);
    float* sBias = sWo + TN * C_;
    __shared__ int s_last;

    const int tid  = threadIdx.x;
    const int wid  = tid >> 5;
    const int lane = tid & 31;
    const int warp_m = wid & 1;
    const int warp_n = wid >> 1;
    const int n0 = blockIdx.x * TN;
    const int m0 = blockIdx.y * TM;

    for (int i = tid; i < TN * C_; i += 128) sWo[i] = Wo[(size_t)n0 * C_ + i];
    if (tid < TN) sBias[tid] = bias[n0 + tid];

    const __nv_bfloat16* __restrict__ Ahi = g_mean_hi + (size_t)m0 * H_;
    const __nv_bfloat16* __restrict__ Alo = g_mean_lo + (size_t)m0 * H_;
    const __nv_bfloat16* __restrict__ Bhi = g_wt_hi + (size_t)n0 * H_;
    const __nv_bfloat16* __restrict__ Blo = g_wt_lo + (size_t)n0 * H_;

    // copy one chunk into stage ck % NSTAGE
    auto issue = [&](int ck) {
        const int st = ck % NSTAGE;
        const int k0 = ck * KC;
        #pragma unroll
        for (int i = 0; i < 4; ++i) {
            const int unit = tid + i * 128;          // 0..511
            const int row = unit >> 3, u = unit & 7;
            const size_t goff = (size_t)row * H_ + k0 + u * 8;
            const int soff = (st * TM + row) * KPAD + u * 8;
            CP16(s2u(sA_hi + soff), Ahi + goff);
            CP16(s2u(sA_lo + soff), Alo + goff);
        }
        #pragma unroll
        for (int i = 0; i < 6; ++i) {
            const int unit = tid + i * 128;          // 0..767
            const int row = unit >> 3, u = unit & 7;
            const size_t goff = (size_t)row * H_ + k0 + u * 8;
            const int soff = (st * TN + row) * KPAD + u * 8;
            CP16(s2u(sB_hi + soff), Bhi + goff);
            CP16(s2u(sB_lo + soff), Blo + goff);
        }
    };

    issue(0); CP_COMMIT();
    issue(1); CP_COMMIT();
    issue(2); CP_COMMIT();

    float acc[2][6][4] = {};

    #pragma unroll 1
    for (int ck = 0; ck < NCHUNK; ++ck) {
        if (ck + 3 < NCHUNK) {
            asm volatile("cp.async.wait_group 2;" ::: "memory");
        } else {
            asm volatile("cp.async.wait_group 0;" ::: "memory");
        }
        __syncthreads();
        if (ck + 3 < NCHUNK) { issue(ck + 3); CP_COMMIT(); }

        const int abase = (ck % NSTAGE) * A_STAGE;
        const int bbase = (ck % NSTAGE) * B_STAGE;
        #pragma unroll
        for (int ks = 0; ks < KC / 16; ++ks) {
            const int kw = ks * 16;
            uint32_t ah[2][4], al[2][4], bh[3][4], bl[3][4];
            #pragma unroll
            for (int mt = 0; mt < 2; ++mt) {
                int row = warp_m * 32 + mt * 16 + (lane & 15);
                int col = kw + ((lane >> 4) << 3);
                ldsm_x4(ah[mt], s2u(sA_hi + abase + row * KPAD + col));
                ldsm_x4(al[mt], s2u(sA_lo + abase + row * KPAD + col));
            }
            #pragma unroll
            for (int np = 0; np < 3; ++np) {
                int row = warp_n * 48 + np * 16 + (lane & 7) +
                          ((lane >> 4) << 3);
                int col = kw + (((lane >> 3) & 1) << 3);
                ldsm_x4(bh[np], s2u(sB_hi + bbase + row * KPAD + col));
                ldsm_x4(bl[np], s2u(sB_lo + bbase + row * KPAD + col));
            }
            // PRODUCT-MAJOR issue: 12 independent accumulators between any
            // two MMAs that share an accumulator (was: 3 dependent in a row).
            #pragma unroll
            for (int p = 0; p < 3; ++p) {
                #pragma unroll
                for (int mt = 0; mt < 2; ++mt) {
                    #pragma unroll
                    for (int nt = 0; nt < 6; ++nt) {
                        const uint32_t* ap = (p == 2) ? al[mt] : ah[mt];
                        const uint32_t* bp = (p == 1)
                            ? &bl[nt >> 1][(nt & 1) * 2]
                            : &bh[nt >> 1][(nt & 1) * 2];
                        mma_bf16(acc[mt][nt], ap, bp);
                    }
                }
            }
        }
    }

    // ---- epilogue: bias + SELU + partial logits ----
    const float kScale = 1.0507009873554805f;
    const float kAlpha = 1.6732632423543772f;
    float pl[4][C_] = {};
    #pragma unroll
    for (int mt = 0; mt < 2; ++mt) {
        #pragma unroll
        for (int nt = 0; nt < 6; ++nt) {
            #pragma unroll
            for (int e = 0; e < 4; ++e) {
                int col = warp_n * 48 + nt * 8 + (lane & 3) * 2 + (e & 1);
                float x = acc[mt][nt][e] + sBias[col];
                float y = (x > 0.0f) ? x : kAlpha * expm1f(x);
                float h = kScale * y;
                int ridx = mt * 2 + (e >> 1);
                #pragma unroll
                for (int c = 0; c < C_; ++c)
                    pl[ridx][c] = fmaf(h, sWo[col * C_ + c], pl[ridx][c]);
            }
        }
    }
    #pragma unroll
    for (int ridx = 0; ridx < 4; ++ridx)
        #pragma unroll
        for (int c = 0; c < C_; ++c) {
            pl[ridx][c] += __shfl_xor_sync(0xFFFFFFFFu, pl[ridx][c], 1);
            pl[ridx][c] += __shfl_xor_sync(0xFFFFFFFFu, pl[ridx][c], 2);
        }
    if ((lane & 3) == 0) {
        const int slot = blockIdx.x * 2 + warp_n;
        #pragma unroll
        for (int ridx = 0; ridx < 4; ++ridx) {
            int row = m0 + warp_m * 32 + (ridx >> 1) * 16 + (lane >> 2) +
                      (ridx & 1) * 8;
            float* dst = g_partial + ((size_t)slot * NSEG + row) * C_;
            #pragma unroll
            for (int c = 0; c < C_; ++c) dst[c] = pl[ridx][c];
        }
    }

    // ---- fused finish: last CTA per M-tile reduces + softmax ----
    __threadfence();
    __syncthreads();
    if (tid == 0) {
        unsigned int old = atomicAdd(&g_arrive[blockIdx.y], 1u);
        s_last = (old == NTILE_N - 1) ? 1 : 0;
    }
    __syncthreads();
    if (s_last) {
        __threadfence();
        if (tid < TM) {
            const int row = m0 + tid;
            float l[C_];
            #pragma unroll
            for (int c = 0; c < C_; ++c) l[c] = bo[c];
            #pragma unroll
            for (int t = 0; t < NTILE_P; ++t) {
                const float* p = g_partial + ((size_t)t * NSEG + row) * C_;
                #pragma unroll
                for (int c = 0; c < C_; ++c) l[c] += p[c];
            }
            float mx = -INFINITY;
            #pragma unroll
            for (int c = 0; c < C_; ++c) mx = fmaxf(mx, l[c]);
            float sum = 0.0f;
            #pragma unroll
            for (int c = 0; c < C_; ++c) { l[c] = expf(l[c] - mx); sum += l[c]; }
            float inv = 1.0f / sum;
            #pragma unroll
            for (int c = 0; c < C_; ++c)
                out[(size_t)row * C_ + c] = l[c] * inv;
        }
        __syncthreads();
        if (tid == 0) g_arrive[blockIdx.y] = 0u;   // self-reset for replay
    }
}

// ---------------------------------------------------------------------------
// Launch
// ---------------------------------------------------------------------------
extern "C" void kernel_launch(void* const* d_in, const int* in_sizes, int n_in,
                              void* d_out, int out_size) {
    const float* hidden = (const float*)d_in[0];
    const int*   seg    = (const int*)d_in[1];
    int base = (n_in >= 7) ? 3 : 2;
    const float* W_h = (const float*)d_in[base + 0];
    const float* b_h = (const float*)d_in[base + 1];
    const float* W_o = (const float*)d_in[base + 2];
    const float* b_o = (const float*)d_in[base + 3];
    float* out = (float*)d_out;

    cudaFuncSetAttribute(gemm_fused_kernel,
                         cudaFuncAttributeMaxDynamicSharedMemorySize,
                         SMEM_BYTES);

    prep_kernel<<<NSEG + NWPREP, 384>>>(hidden, seg, W_h);

    dim3 gg(NTILE_N, NTILE_M);   // (8, 16) = 128 CTAs
    gemm_fused_kernel<<<gg, 128, SMEM_BYTES>>>(b_h, W_o, b_o, out);
}